// round 10
// baseline (speedup 1.0000x reference)
#include <cuda_runtime.h>

typedef unsigned long long u64;

#define NN 64
#define TT 5
#define VV 64
#define FF 256
#define TMID 2   // T//2
#define ABS2_MASK 0x7FFFFFFF7FFFFFFFULL

__device__ __forceinline__ u64 add2(u64 a, u64 b) {
    u64 d; asm("add.rn.f32x2 %0, %1, %2;" : "=l"(d) : "l"(a), "l"(b)); return d;
}
__device__ __forceinline__ u64 swap2(u64 v) {
    u64 d;
    asm("{.reg .b32 lo, hi; mov.b64 {lo, hi}, %1; mov.b64 %0, {hi, lo};}"
        : "=l"(d) : "l"(v));
    return d;
}
__device__ __forceinline__ float lo2(u64 v) { return __uint_as_float((unsigned)v); }
__device__ __forceinline__ float hi2(u64 v) { return __uint_as_float((unsigned)(v >> 32)); }

// Grid = 128 (64 graphs x 2 halves), 512 threads = 16 warps.
// Key algebraic move: a_f >= 0, so a_f*|x_i - x_j| == |a_f*x_i - a_f*x_j|.
// We stage y = a .* x (and -y), removing the per-f 'a' load and turning every
// fma-pipe op into a 2-source packed add.
//
// Block owns 32 complete rows i of graph n's 64x64 similarity matrix; the
// column-sum denominator equals the row sum by exact (bitwise) symmetry of S.
// Warp = (tile = w&3 -> rows tile*8..+7, fq = w>>2 -> f in [fq*64, fq*64+64)).
// Lane owns j = 2*lane, 2*lane+1; diagonal f32x2 packing, 8 accumulators.
// f-quarters merge via packed adds through smem; fq==0 warps do the epilogue.
__global__ __launch_bounds__(512, 1)
void gl_kernel(const float* __restrict__ x,
               const float* __restrict__ a,
               float* __restrict__ out) {
    extern __shared__ float sm[];
    float* xsT = sm;                          // [FF][VV]  y = a.*x (transposed)
    float* xsN = sm + FF * VV;                // [FF][VV] -y
    float* a_s = sm + 2 * FF * VV;            // [FF]
    u64*   ex  = (u64*)(a_s + FF);            // [8][3][4][32] partials, 24 KB

    const int b    = blockIdx.x;
    const int n    = b >> 1;
    const int half = b & 1;
    const int tid  = threadIdx.x;
    const int lane = tid & 31;
    const int warp = tid >> 5;

    const float* xm = x + ((size_t)n * TT + TMID) * (size_t)(VV * FF);

    if (tid < FF) a_s[tid] = a[tid];
    __syncthreads();

    // ---- Stage: xsT[f*VV+v] = a[f]*xm[v*FF+f], xsN = negated. ----
    // v = idx&63 gives 32 distinct v per warp -> conflict-free STS.
    const float4* x4 = (const float4*)xm;
    #pragma unroll
    for (int idx = tid; idx < VV * (FF / 4); idx += 512) {
        int v  = idx & 63;
        int f4 = idx >> 6;
        float4 val = x4[v * (FF / 4) + f4];
        int f = f4 * 4;
        float y0 = a_s[f + 0] * val.x;
        float y1 = a_s[f + 1] * val.y;
        float y2 = a_s[f + 2] * val.z;
        float y3 = a_s[f + 3] * val.w;
        xsT[(f + 0) * VV + v] =  y0;  xsN[(f + 0) * VV + v] = -y0;
        xsT[(f + 1) * VV + v] =  y1;  xsN[(f + 1) * VV + v] = -y1;
        xsT[(f + 2) * VV + v] =  y2;  xsN[(f + 2) * VV + v] = -y2;
        xsT[(f + 3) * VV + v] =  y3;  xsN[(f + 3) * VV + v] = -y3;
    }
    __syncthreads();

    const int tile   = warp & 3;                // rows tile*8 .. tile*8+7
    const int fq     = warp >> 2;               // f-quarter 0..3
    const int i_base = half * 32 + tile * 8;    // 32B-aligned in xsT rows
    const int j0     = lane << 1;

    const float* pT = xsT + (fq * (FF / 4)) * VV + i_base;
    const float* pN = xsN + (fq * (FF / 4)) * VV + j0;

    u64 acc[8];
    #pragma unroll
    for (int k = 0; k < 8; k++) acc[k] = 0;

    // ---- Main loop: 64 f per warp; 2 LDS.128 + 1 LDS.64, 24 packed ops,
    //      covering 512 pair-f per iteration. ----
    #pragma unroll 4
    for (int f = 0; f < FF / 4; f++) {
        ulonglong2 xiA = *(const ulonglong2*)pT;        // (y_i0,y_i1),(y_i2,y_i3)
        ulonglong2 xiB = *(const ulonglong2*)(pT + 4);  // (y_i4,y_i5),(y_i6,y_i7)
        u64 nj  = *(const u64*)pN;                      // (-y_j0,-y_j1)
        u64 njr = swap2(nj);                            // (-y_j1,-y_j0)

        acc[0] = add2(acc[0], add2(xiA.x, nj ) & ABS2_MASK); // (i0,j0)(i1,j1)
        acc[1] = add2(acc[1], add2(xiA.x, njr) & ABS2_MASK); // (i0,j1)(i1,j0)
        acc[2] = add2(acc[2], add2(xiA.y, nj ) & ABS2_MASK); // (i2,j0)(i3,j1)
        acc[3] = add2(acc[3], add2(xiA.y, njr) & ABS2_MASK); // (i2,j1)(i3,j0)
        acc[4] = add2(acc[4], add2(xiB.x, nj ) & ABS2_MASK); // (i4,j0)(i5,j1)
        acc[5] = add2(acc[5], add2(xiB.x, njr) & ABS2_MASK); // (i4,j1)(i5,j0)
        acc[6] = add2(acc[6], add2(xiB.y, nj ) & ABS2_MASK); // (i6,j0)(i7,j1)
        acc[7] = add2(acc[7], add2(xiB.y, njr) & ABS2_MASK); // (i6,j1)(i7,j0)

        pT += VV; pN += VV;
    }

    // ---- Merge f-quarters: fq>0 publish, fq==0 adds. ----
    // ex index: k*384 + (fq-1)*128 + tile*32 + lane  (8B lane stride: no conflicts)
    if (fq) {
        u64* p = ex + (fq - 1) * 128 + tile * 32 + lane;
        #pragma unroll
        for (int k = 0; k < 8; k++) p[k * 384] = acc[k];
    }
    __syncthreads();
    if (fq) return;

    {
        const u64* p = ex + tile * 32 + lane;
        #pragma unroll
        for (int k = 0; k < 8; k++) {
            u64 s01 = add2(p[k * 384], p[k * 384 + 128]);
            acc[k]  = add2(add2(acc[k], p[k * 384 + 256]), s01);
        }
    }

    // ---- exp, per-row warp reduction (row sum == reference column sum) ----
    const float LOG2E = 1.4426950408889634f;
    float sl[8], sh[8];
    #pragma unroll
    for (int k = 0; k < 8; k++) {
        sl[k] = exp2f(lo2(acc[k]) * LOG2E);
        sh[k] = exp2f(hi2(acc[k]) * LOG2E);
    }
    // row 2r  : j0 -> sl[2r],   j1 -> sl[2r+1]
    // row 2r+1: j0 -> sh[2r+1], j1 -> sh[2r]
    float p[8];
    #pragma unroll
    for (int r = 0; r < 4; r++) {
        p[2 * r]     = sl[2 * r] + sl[2 * r + 1];
        p[2 * r + 1] = sh[2 * r] + sh[2 * r + 1];
    }
    #pragma unroll
    for (int off = 16; off > 0; off >>= 1) {
        #pragma unroll
        for (int r = 0; r < 8; r++)
            p[r] += __shfl_xor_sync(0xFFFFFFFFu, p[r], off);
    }

    float* ob = out + ((size_t)(n * VV + i_base)) * VV + j0;
    #pragma unroll
    for (int r = 0; r < 4; r++) {
        float inv0 = 1.0f / p[2 * r];
        float inv1 = 1.0f / p[2 * r + 1];
        *(float2*)(ob + (2 * r)     * VV) =
            make_float2(sl[2 * r] * inv0, sl[2 * r + 1] * inv0);
        *(float2*)(ob + (2 * r + 1) * VV) =
            make_float2(sh[2 * r + 1] * inv1, sh[2 * r] * inv1);
    }
}

extern "C" void kernel_launch(void* const* d_in, const int* in_sizes, int n_in,
                              void* d_out, int out_size) {
    const float* x = (const float*)d_in[0];   // (64,5,64,256) float32
    const float* a = (const float*)d_in[1];   // (256,1) float32
    float* out = (float*)d_out;               // (64,64,64) float32

    const int smem_bytes = 2 * FF * VV * (int)sizeof(float)   // xsT + xsN
                         + FF * (int)sizeof(float)            // a_s
                         + 8 * 384 * (int)sizeof(u64);        // ex (24 KB)
    cudaFuncSetAttribute(gl_kernel, cudaFuncAttributeMaxDynamicSharedMemorySize,
                         smem_bytes);
    gl_kernel<<<NN * 2, 512, smem_bytes>>>(x, a, out);
}